// round 17
// baseline (speedup 1.0000x reference)
#include <cuda_runtime.h>
#include <cuda_bf16.h>

// One-hot: x [8,1024] int32 -> out [8,1024,32000] fp32 (1.048 GB of stores).
//
// Tail-free tenth-row variant of the converged design: 8000 f4/row = 10
// chunks x 800 f4; 800 = 160 threads x 5 iters EXACTLY -> no predicated
// tail iteration (the 1/16 variant wastes 116/128 slots in its 4th iter).
// grid = 81920 fine-grained self-balancing blocks; evict-first __stcs
// streaming stores; per-row index is a uniform broadcast issued ahead of
// the store stream. The 1.0f overwrite is done by the exact thread that
// zeroed that slot (tid == o % 160): same-thread same-address stores are
// program-ordered, so no fence, no second kernel.
//
// Roofline evidence (9 benches): STG.128(.cs) / STG.256 / .wt / driver
// memset all ~7.2 TB/s (~91% of spec); granularity curve flat below 1/8;
// single-wave persistent regressed 25%; residual ~5 us over the 131 us
// spec floor is DRAM refresh/write-turnaround.

static constexpr int NUM_CLASS = 32000;
static constexpr int NC4       = NUM_CLASS / 4;    // 8000 float4 per row
static constexpr int ROWS      = 8 * 1024;         // 8192
static constexpr int SPLITS    = 10;
static constexpr int CHUNK     = NC4 / SPLITS;     // 800 float4 per block
static constexpr int THREADS   = 160;              // 5 warps
static constexpr int ITERS     = CHUNK / THREADS;  // 5, exact — no tail

__global__ void __launch_bounds__(THREADS)
onehot_tenth_kernel(const int* __restrict__ x, float4* __restrict__ out)
{
    const int row = blockIdx.x / SPLITS;
    const int c   = blockIdx.x - row * SPLITS;
    const int tid = threadIdx.x;

    const int t = __ldg(x + row);                  // broadcast; stores don't wait

    float4* p = out + (long long)row * NC4 + c * CHUNK;
    const float4 z = make_float4(0.f, 0.f, 0.f, 0.f);

#pragma unroll
    for (int i = 0; i < ITERS; ++i) {
        __stcs(p + i * THREADS + tid, z);          // evict-first streaming store
    }

    // hot-slot overwrite: offset of the hot float4 within this chunk
    const int o = (t >> 2) - c * CHUNK;
    if (o >= 0 && o < CHUNK && (o % THREADS) == tid) {
        reinterpret_cast<float*>(p + o)[t & 3] = 1.0f;  // same thread zeroed p[o]
    }
}

extern "C" void kernel_launch(void* const* d_in, const int* in_sizes, int n_in,
                              void* d_out, int out_size)
{
    const int* x = (const int*)d_in[0];
    onehot_tenth_kernel<<<ROWS * SPLITS, THREADS>>>(x, (float4*)d_out);
}